// round 14
// baseline (speedup 1.0000x reference)
#include <cuda_runtime.h>
#include <cuda_fp16.h>
#include <cstdint>

// ---------------- problem constants ----------------
#define N_ATOMS   500000
#define N_PER_DEG 125000
#define NODE      128
#define EDGE      64
#define OUT_C     128
#define ASUM_C    320          // halves per row: [0:128) atom sum | [128:192) bond sum | [192:320) self
#define TILE_M    128
#define N_TILES   977          // ceil(125000/128)
#define BN_EPS    1e-5f

__device__ __forceinline__ uint32_t pack_f16x2(float lo, float hi) {
    uint32_t r;
    asm("cvt.rn.f16x2.f32 %0, %1, %2;" : "=r"(r) : "f"(hi), "f"(lo));
    return r;
}

__device__ __forceinline__ void mma_m16n8k16_f16(float d[4], const uint32_t a[4],
                                                 uint32_t b0, uint32_t b1) {
    asm volatile(
        "mma.sync.aligned.m16n8k16.row.col.f32.f16.f16.f32 "
        "{%0,%1,%2,%3}, {%4,%5,%6,%7}, {%8,%9}, {%0,%1,%2,%3};"
        : "+f"(d[0]), "+f"(d[1]), "+f"(d[2]), "+f"(d[3])
        : "r"(a[0]), "r"(a[1]), "r"(a[2]), "r"(a[3]), "r"(b0), "r"(b1));
}

__device__ __forceinline__ void ldmatrix_x4(uint32_t a[4], uint32_t addr) {
    asm volatile(
        "ldmatrix.sync.aligned.m8n8.x4.shared.b16 {%0,%1,%2,%3}, [%4];"
        : "=r"(a[0]), "=r"(a[1]), "=r"(a[2]), "=r"(a[3])
        : "r"(addr));
}

// cp.async helpers
__device__ __forceinline__ uint32_t smem_u32(const void* p) {
    uint32_t a;
    asm("{ .reg .u64 t; cvta.to.shared.u64 t, %1; cvt.u32.u64 %0, t; }" : "=r"(a) : "l"(p));
    return a;
}
#define CP_ASYNC16(dst, src) \
    asm volatile("cp.async.cg.shared.global [%0], [%1], 16;" :: "r"(dst), "l"(src) : "memory")
#define CP_COMMIT() asm volatile("cp.async.commit_group;" ::: "memory")
#define CP_WAIT1()  asm volatile("cp.async.wait_group 1;" ::: "memory")
#define CP_WAIT0()  asm volatile("cp.async.wait_group 0;" ::: "memory")

// ---------------- device scratch (allocation-free) ----------------
__device__ __half g_Asum[(size_t)N_ATOMS * ASUM_C];   // 320 MB, fp16 A (incl. self)
// W in fp16 B-fragment order. Per degree, per kstep t (0..19, K=16 each), per n (0..127),
// per la3 (0..3): 4 halves = { k=t*16+2*la3, +1, t*16+8+2*la3, +1 } (reg0 pair, reg1 pair).
#define WP_PER_DEG (20 * 128 * 16)                    // 40960 halves
__device__ __half g_Wp[4][WP_PER_DEG];
__device__ float g_sum[OUT_C];
__device__ float g_sumsq[OUT_C];
__device__ float g_mean[OUT_C];
__device__ float g_istd[OUT_C];

// ---------------- K0: zero stats ----------------
__global__ void zero_stats_kernel() {
    if (threadIdx.x < OUT_C) { g_sum[threadIdx.x] = 0.f; g_sumsq[threadIdx.x] = 0.f; }
}

// ---------------- W permute/convert (fp16 fragment order) ----------------
__global__ void wconv_kernel(const float* __restrict__ W1, const float* __restrict__ W2,
                             const float* __restrict__ W3, const float* __restrict__ W4,
                             const float* __restrict__ Wself) {
    int idx = blockIdx.x * blockDim.x + threadIdx.x;
    if (idx >= 4 * WP_PER_DEG) return;
    int d   = idx / WP_PER_DEG;
    int rem = idx - d * WP_PER_DEG;
    int h   = rem & 3;               // which of the 4 halves in the lane's uint2
    int la3 = (rem >> 2) & 3;        // lane&3
    int n   = (rem >> 4) & 127;
    int t   = rem >> 11;             // kstep 0..19
    int k   = t * 16 + ((h < 2) ? (la3 * 2 + h) : (8 + la3 * 2 + (h - 2)));
    const float* Wd = (d == 0) ? W1 : (d == 1) ? W2 : (d == 2) ? W3 : W4;
    float v = (k < 192) ? __ldg(Wd + n * 192 + k) : __ldg(Wself + n * 128 + (k - 192));
    g_Wp[d][rem] = __float2half_rn(v);
}

// ---------------- Phase 1: gather + sum (+self) -> fp16 g_Asum ----------------
template <int DEG>
__device__ __forceinline__
void gather_row(const float* __restrict__ atom_repr, const float* __restrict__ bond_repr,
                const int* __restrict__ ap, const int* __restrict__ bp,
                int rid, int selfrow, __half* __restrict__ dst, int lane) {
    int ai[DEG], bi[DEG];
#pragma unroll
    for (int j = 0; j < DEG; j++) ai[j] = __ldg(ap + rid * DEG + j);
#pragma unroll
    for (int j = 0; j < DEG; j++) bi[j] = __ldg(bp + rid * DEG + j);

    float4 va[DEG];
    float2 vb[DEG];
#pragma unroll
    for (int j = 0; j < DEG; j++)
        va[j] = __ldg((const float4*)(atom_repr + (size_t)ai[j] * NODE) + lane);
#pragma unroll
    for (int j = 0; j < DEG; j++)
        vb[j] = __ldg((const float2*)(bond_repr + (size_t)bi[j] * EDGE) + lane);
    float4 u = __ldg((const float4*)(atom_repr + (size_t)selfrow * NODE) + lane);

    float4 s = va[0];
    float2 t = vb[0];
#pragma unroll
    for (int j = 1; j < DEG; j++) {
        s.x += va[j].x; s.y += va[j].y; s.z += va[j].z; s.w += va[j].w;
        t.x += vb[j].x; t.y += vb[j].y;
    }
    uint2 pa = make_uint2(pack_f16x2(s.x, s.y), pack_f16x2(s.z, s.w));
    uint32_t pb = pack_f16x2(t.x, t.y);
    uint2 pu = make_uint2(pack_f16x2(u.x, u.y), pack_f16x2(u.z, u.w));
    *(uint2*)(dst + lane * 4)           = pa;   // atom sum: halves [0,128)
    *(uint32_t*)(dst + 128 + lane * 2)  = pb;   // bond sum: halves [128,192)
    *(uint2*)(dst + 192 + lane * 4)     = pu;   // self:     halves [192,320)
}

__global__ __launch_bounds__(256)
void gather_kernel(const float* __restrict__ atom_repr, const float* __restrict__ bond_repr,
                   const int* __restrict__ a1, const int* __restrict__ a2,
                   const int* __restrict__ a3, const int* __restrict__ a4,
                   const int* __restrict__ b1, const int* __restrict__ b2,
                   const int* __restrict__ b3, const int* __restrict__ b4) {
    const int w = (blockIdx.x * 256 + threadIdx.x) >> 5;   // one warp per row
    if (w >= N_ATOMS) return;
    const int lane = threadIdx.x & 31;
    const int deg = w / N_PER_DEG;
    const int rid = w - deg * N_PER_DEG;
    __half* dst = g_Asum + (size_t)w * ASUM_C;
    switch (deg) {
        case 0:  gather_row<1>(atom_repr, bond_repr, a1, b1, rid, w, dst, lane); break;
        case 1:  gather_row<2>(atom_repr, bond_repr, a2, b2, rid, w, dst, lane); break;
        case 2:  gather_row<3>(atom_repr, bond_repr, a3, b3, rid, w, dst, lane); break;
        default: gather_row<4>(atom_repr, bond_repr, a4, b4, rid, w, dst, lane); break;
    }
}

// ---------------- Phase 2: fp16 pipelined GEMM + bias + BN stats ----------------
// 128 threads, 4 warps; warp tile 64(M) x 64(N), grid 2x2. K=320 in 5 chunks of 64
// (4 ksteps of 16), all A from fp16 g_Asum. 3-stage cp.async pipeline.
// Stage = A[128 rows][144 B] (128 data B + pad; banks 36r+4s mod 32 conflict-free)
//       + W[2 ksteps... 4 ksteps = 16384 B].
#define P2_AROW_B   144                              // bytes per A row (64 halves + pad)
#define P2_A_BYTES  (128 * P2_AROW_B)                // 18432
#define P2_W_BYTES  (4 * 128 * 16 * 2)               // 16384 (4 ksteps)
#define P2_STAGE_B  (P2_A_BYTES + P2_W_BYTES)        // 34816
#define P2_OFF_STATS (3 * P2_STAGE_B)                // 104448
#define P2_SMEM      (P2_OFF_STATS + 1024)           // 105472

__global__ __launch_bounds__(128, 2)
void gemm_kernel(const float* __restrict__ bias,
                 float* __restrict__ out) {
    extern __shared__ char smem[];
    float* s_sum = (float*)(smem + P2_OFF_STATS);
    float* s_sq  = s_sum + OUT_C;

    const int tid  = threadIdx.x;
    const int wid  = tid >> 5;
    const int lane = tid & 31;
    const int warp_m = wid & 1;        // 2 M-warps x 64 rows
    const int warp_n = wid >> 1;       // 2 N-warps x 64 cols

    const int d = blockIdx.x & 3;
    const int tile_base = (blockIdx.x >> 2) * TILE_M;
    const int deg_base = d * N_PER_DEG;
    const __half* __restrict__ Wp = g_Wp[d];

    s_sum[tid] = 0.f;                  // blockDim == OUT_C == 128
    s_sq[tid]  = 0.f;

    const uint32_t smem_addr = smem_u32(smem);

    auto issue_stage = [&](int c, int s) {
        const uint32_t aoff = smem_addr + (uint32_t)(s * P2_STAGE_B);
        const uint32_t woff = aoff + (uint32_t)P2_A_BYTES;
#pragma unroll
        for (int i = 0; i < 8; i++) {
            int idx = tid + i * 128;       // 0..1023
            int row = idx >> 3;
            int q   = idx & 7;             // 16B segment within the 128B row chunk
            int rg  = tile_base + row;
            if (rg >= N_PER_DEG) rg = N_PER_DEG - 1;
            const __half* asrc = g_Asum + (size_t)(deg_base + rg) * ASUM_C + c * 64 + q * 8;
            CP_ASYNC16(aoff + (uint32_t)(row * P2_AROW_B + q * 16), asrc);
        }
#pragma unroll
        for (int i = 0; i < 8; i++) {
            int idx = tid + i * 128;       // 0..1023, 16B each covers the 16384B W block
            CP_ASYNC16(woff + (uint32_t)idx * 16, Wp + (size_t)c * 8192 + idx * 8);
        }
        CP_COMMIT();
    };

    float acc[4][8][4];
#pragma unroll
    for (int mi = 0; mi < 4; mi++)
#pragma unroll
        for (int nb = 0; nb < 8; nb++)
#pragma unroll
            for (int i = 0; i < 4; i++) acc[mi][nb][i] = 0.f;

    issue_stage(0, 0);
    issue_stage(1, 1);

    // ldmatrix per-lane A address (bytes, within stage A block):
    //   lanes 0-7: rows r0-7 col 0 | 8-15: rows 8-15 col 0 | 16-23: rows 0-7 col 16B | 24-31: rows 8-15 col 16B
    const int lm_row = warp_m * 64 + (lane & 7) + ((lane >> 3) & 1) * 8;
    const uint32_t lm_base = (uint32_t)(lm_row * P2_AROW_B + (lane >> 4) * 16);

    // B fragment uint2 offset within a kstep block (512 uint2):
    //   (warp_n*64 + nb*8 + (lane>>2))*4 + (lane&3)
    const int bfrag_off = (warp_n * 64 + (lane >> 2)) * 4 + (lane & 3);

    int s = 0;
#pragma unroll
    for (int c = 0; c < 5; c++) {
        if (c < 4) CP_WAIT1(); else CP_WAIT0();
        __syncthreads();
        if (c + 2 < 5) issue_stage(c + 2, (c + 2) % 3);

        const uint32_t a_stage = smem_addr + (uint32_t)(s * P2_STAGE_B);
        const uint2* Wf = (const uint2*)(smem + (size_t)(s * P2_STAGE_B + P2_A_BYTES));

#pragma unroll
        for (int ks = 0; ks < 4; ks++) {
            uint32_t a[4][4];
#pragma unroll
            for (int mi = 0; mi < 4; mi++)
                ldmatrix_x4(a[mi], a_stage + lm_base + (uint32_t)(mi * 16 * P2_AROW_B + ks * 32));
            const uint2* wst = Wf + ks * 512 + bfrag_off;
#pragma unroll
            for (int nb = 0; nb < 8; nb++) {
                uint2 b = wst[nb * 32];                      // nb*8 n-rows * 4 uint2
#pragma unroll
                for (int mi = 0; mi < 4; mi++)
                    mma_m16n8k16_f16(acc[mi][nb], a[mi], b.x, b.y);
            }
        }
        s = (s == 2) ? 0 : s + 1;
    }

    // ---- epilogue: bias + streaming store + fused BN partial stats ----
#pragma unroll
    for (int nb = 0; nb < 8; nb++) {
        const int col0 = warp_n * 64 + nb * 8 + (lane & 3) * 2;
        const float bv0 = __ldg(bias + col0);
        const float bv1 = __ldg(bias + col0 + 1);
        float ps0 = 0.f, ps1 = 0.f, pq0 = 0.f, pq1 = 0.f;
#pragma unroll
        for (int mi = 0; mi < 4; mi++) {
            int gr0 = tile_base + warp_m * 64 + mi * 16 + (lane >> 2);
            float x00 = acc[mi][nb][0] + bv0;
            float x01 = acc[mi][nb][1] + bv1;
            float x10 = acc[mi][nb][2] + bv0;
            float x11 = acc[mi][nb][3] + bv1;
            if (gr0 < N_PER_DEG) {
                __stcs((float2*)(out + (size_t)(deg_base + gr0) * OUT_C + col0),
                       make_float2(x00, x01));
                ps0 += x00; ps1 += x01; pq0 += x00 * x00; pq1 += x01 * x01;
            }
            if (gr0 + 8 < N_PER_DEG) {
                __stcs((float2*)(out + (size_t)(deg_base + gr0 + 8) * OUT_C + col0),
                       make_float2(x10, x11));
                ps0 += x10; ps1 += x11; pq0 += x10 * x10; pq1 += x11 * x11;
            }
        }
#pragma unroll
        for (int m = 4; m < 32; m <<= 1) {
            ps0 += __shfl_xor_sync(0xffffffffu, ps0, m);
            ps1 += __shfl_xor_sync(0xffffffffu, ps1, m);
            pq0 += __shfl_xor_sync(0xffffffffu, pq0, m);
            pq1 += __shfl_xor_sync(0xffffffffu, pq1, m);
        }
        if ((lane >> 2) == 0) {
            atomicAdd(&s_sum[col0], ps0);
            atomicAdd(&s_sum[col0 + 1], ps1);
            atomicAdd(&s_sq[col0], pq0);
            atomicAdd(&s_sq[col0 + 1], pq1);
        }
    }

    __syncthreads();
    atomicAdd(&g_sum[tid], s_sum[tid]);
    atomicAdd(&g_sumsq[tid], s_sq[tid]);
}

// ---------------- finalize + BN/ReLU ----------------
__global__ void finalize_stats_kernel() {
    int c = threadIdx.x;
    if (c < OUT_C) {
        float mean = g_sum[c] * (1.0f / N_ATOMS);
        float var = g_sumsq[c] * (1.0f / N_ATOMS) - mean * mean;
        g_mean[c] = mean;
        g_istd[c] = rsqrtf(var + BN_EPS);
    }
}

__global__ void bn_relu_kernel(float4* __restrict__ x, int n4) {
    int t = blockIdx.x * blockDim.x + threadIdx.x;
    int stride = gridDim.x * blockDim.x;   // multiple of 32
    int c = (t & 31) * 4;
    float m0 = g_mean[c + 0], m1 = g_mean[c + 1], m2 = g_mean[c + 2], m3 = g_mean[c + 3];
    float i0 = g_istd[c + 0], i1 = g_istd[c + 1], i2 = g_istd[c + 2], i3 = g_istd[c + 3];
    for (int i = t; i < n4; i += stride) {
        float4 v = __ldcs(&x[i]);
        v.x = fmaxf((v.x - m0) * i0, 0.f);
        v.y = fmaxf((v.y - m1) * i1, 0.f);
        v.z = fmaxf((v.z - m2) * i2, 0.f);
        v.w = fmaxf((v.w - m3) * i3, 0.f);
        __stcs(&x[i], v);
    }
}

// ---------------- launch ----------------
extern "C" void kernel_launch(void* const* d_in, const int* in_sizes, int n_in,
                              void* d_out, int out_size) {
    (void)n_in; (void)out_size;

    const float* atom_repr = (const float*)d_in[0];
    const float* bond_repr = (const float*)d_in[1];
    const int* aidx[4];
    const int* bidx[4];
    const float* W[4];

    if (in_sizes[4] == OUT_C * (NODE + EDGE)) {
        for (int d = 0; d < 4; d++) {
            aidx[d] = (const int*)d_in[2 + 3 * d];
            bidx[d] = (const int*)d_in[3 + 3 * d];
            W[d]    = (const float*)d_in[4 + 3 * d];
        }
    } else {
        for (int d = 0; d < 4; d++) {
            aidx[d] = (const int*)d_in[2 + d];
            bidx[d] = (const int*)d_in[6 + d];
            W[d]    = (const float*)d_in[10 + d];
        }
    }
    const float* Wself = (const float*)d_in[14];
    const float* bias  = (const float*)d_in[15];
    float* out = (float*)d_out;

    cudaFuncSetAttribute(gemm_kernel, cudaFuncAttributeMaxDynamicSharedMemorySize, P2_SMEM);

    zero_stats_kernel<<<1, 128>>>();
    wconv_kernel<<<(4 * WP_PER_DEG + 255) / 256, 256>>>(W[0], W[1], W[2], W[3], Wself);
    gather_kernel<<<(N_ATOMS * 32) / 256, 256>>>(
        atom_repr, bond_repr,
        aidx[0], aidx[1], aidx[2], aidx[3],
        bidx[0], bidx[1], bidx[2], bidx[3]);
    gemm_kernel<<<4 * N_TILES, 128, P2_SMEM>>>(bias, out);
    finalize_stats_kernel<<<1, 128>>>();
    const int n4 = (N_ATOMS * OUT_C) / 4;
    bn_relu_kernel<<<2960, 256>>>((float4*)out, n4);
}

// round 15
// speedup vs baseline: 1.0340x; 1.0340x over previous
#include <cuda_runtime.h>
#include <cuda_fp16.h>
#include <cstdint>

// ---------------- problem constants ----------------
#define N_ATOMS   500000
#define N_PER_DEG 125000
#define NODE      128
#define EDGE      64
#define OUT_C     128
#define ASUM_C    320          // halves per row: [0:128) atom sum | [128:192) bond sum | [192:320) self
#define TILE_M    128
#define N_TILES   977          // ceil(125000/128)
#define BN_EPS    1e-5f

__device__ __forceinline__ uint32_t pack_f16x2(float lo, float hi) {
    uint32_t r;
    asm("cvt.rn.f16x2.f32 %0, %1, %2;" : "=r"(r) : "f"(hi), "f"(lo));
    return r;
}

__device__ __forceinline__ void mma_m16n8k16_f16(float d[4], const uint32_t a[4],
                                                 uint32_t b0, uint32_t b1) {
    asm volatile(
        "mma.sync.aligned.m16n8k16.row.col.f32.f16.f16.f32 "
        "{%0,%1,%2,%3}, {%4,%5,%6,%7}, {%8,%9}, {%0,%1,%2,%3};"
        : "+f"(d[0]), "+f"(d[1]), "+f"(d[2]), "+f"(d[3])
        : "r"(a[0]), "r"(a[1]), "r"(a[2]), "r"(a[3]), "r"(b0), "r"(b1));
}

__device__ __forceinline__ void ldmatrix_x4(uint32_t a[4], uint32_t addr) {
    asm volatile(
        "ldmatrix.sync.aligned.m8n8.x4.shared.b16 {%0,%1,%2,%3}, [%4];"
        : "=r"(a[0]), "=r"(a[1]), "=r"(a[2]), "=r"(a[3])
        : "r"(addr));
}

// cp.async helpers
__device__ __forceinline__ uint32_t smem_u32(const void* p) {
    uint32_t a;
    asm("{ .reg .u64 t; cvta.to.shared.u64 t, %1; cvt.u32.u64 %0, t; }" : "=r"(a) : "l"(p));
    return a;
}
#define CP_ASYNC16(dst, src) \
    asm volatile("cp.async.cg.shared.global [%0], [%1], 16;" :: "r"(dst), "l"(src) : "memory")
#define CP_COMMIT() asm volatile("cp.async.commit_group;" ::: "memory")
#define CP_WAIT1()  asm volatile("cp.async.wait_group 1;" ::: "memory")
#define CP_WAIT0()  asm volatile("cp.async.wait_group 0;" ::: "memory")

// ---------------- device scratch (allocation-free) ----------------
__device__ __half g_Asum[(size_t)N_ATOMS * ASUM_C];   // 320 MB, fp16 A (incl. self)
__device__ __half g_x[(size_t)N_ATOMS * OUT_C];       // 128 MB, fp16 pre-BN activations
// W in fp16 B-fragment order. Per degree, per kstep t (0..19, K=16 each), per n (0..127),
// per la3 (0..3): 4 halves = { k=t*16+2*la3, +1, t*16+8+2*la3, +1 } (reg0 pair, reg1 pair).
#define WP_PER_DEG (20 * 128 * 16)                    // 40960 halves
__device__ __half g_Wp[4][WP_PER_DEG];
__device__ float g_sum[OUT_C];
__device__ float g_sumsq[OUT_C];
__device__ float g_mean[OUT_C];
__device__ float g_istd[OUT_C];

// ---------------- K0: zero stats ----------------
__global__ void zero_stats_kernel() {
    if (threadIdx.x < OUT_C) { g_sum[threadIdx.x] = 0.f; g_sumsq[threadIdx.x] = 0.f; }
}

// ---------------- W permute/convert (fp16 fragment order) ----------------
__global__ void wconv_kernel(const float* __restrict__ W1, const float* __restrict__ W2,
                             const float* __restrict__ W3, const float* __restrict__ W4,
                             const float* __restrict__ Wself) {
    int idx = blockIdx.x * blockDim.x + threadIdx.x;
    if (idx >= 4 * WP_PER_DEG) return;
    int d   = idx / WP_PER_DEG;
    int rem = idx - d * WP_PER_DEG;
    int h   = rem & 3;               // which of the 4 halves in the lane's uint2
    int la3 = (rem >> 2) & 3;        // lane&3
    int n   = (rem >> 4) & 127;
    int t   = rem >> 11;             // kstep 0..19
    int k   = t * 16 + ((h < 2) ? (la3 * 2 + h) : (8 + la3 * 2 + (h - 2)));
    const float* Wd = (d == 0) ? W1 : (d == 1) ? W2 : (d == 2) ? W3 : W4;
    float v = (k < 192) ? __ldg(Wd + n * 192 + k) : __ldg(Wself + n * 128 + (k - 192));
    g_Wp[d][rem] = __float2half_rn(v);
}

// ---------------- Phase 1: gather + sum (+self) -> fp16 g_Asum ----------------
template <int DEG>
__device__ __forceinline__
void gather_row(const float* __restrict__ atom_repr, const float* __restrict__ bond_repr,
                const int* __restrict__ ap, const int* __restrict__ bp,
                int rid, int selfrow, __half* __restrict__ dst, int lane) {
    int ai[DEG], bi[DEG];
#pragma unroll
    for (int j = 0; j < DEG; j++) ai[j] = __ldg(ap + rid * DEG + j);
#pragma unroll
    for (int j = 0; j < DEG; j++) bi[j] = __ldg(bp + rid * DEG + j);

    float4 va[DEG];
    float2 vb[DEG];
#pragma unroll
    for (int j = 0; j < DEG; j++)
        va[j] = __ldg((const float4*)(atom_repr + (size_t)ai[j] * NODE) + lane);
#pragma unroll
    for (int j = 0; j < DEG; j++)
        vb[j] = __ldg((const float2*)(bond_repr + (size_t)bi[j] * EDGE) + lane);
    float4 u = __ldg((const float4*)(atom_repr + (size_t)selfrow * NODE) + lane);

    float4 s = va[0];
    float2 t = vb[0];
#pragma unroll
    for (int j = 1; j < DEG; j++) {
        s.x += va[j].x; s.y += va[j].y; s.z += va[j].z; s.w += va[j].w;
        t.x += vb[j].x; t.y += vb[j].y;
    }
    uint2 pa = make_uint2(pack_f16x2(s.x, s.y), pack_f16x2(s.z, s.w));
    uint32_t pb = pack_f16x2(t.x, t.y);
    uint2 pu = make_uint2(pack_f16x2(u.x, u.y), pack_f16x2(u.z, u.w));
    *(uint2*)(dst + lane * 4)           = pa;   // atom sum: halves [0,128)
    *(uint32_t*)(dst + 128 + lane * 2)  = pb;   // bond sum: halves [128,192)
    *(uint2*)(dst + 192 + lane * 4)     = pu;   // self:     halves [192,320)
}

__global__ __launch_bounds__(256)
void gather_kernel(const float* __restrict__ atom_repr, const float* __restrict__ bond_repr,
                   const int* __restrict__ a1, const int* __restrict__ a2,
                   const int* __restrict__ a3, const int* __restrict__ a4,
                   const int* __restrict__ b1, const int* __restrict__ b2,
                   const int* __restrict__ b3, const int* __restrict__ b4) {
    const int w = (blockIdx.x * 256 + threadIdx.x) >> 5;   // one warp per row
    if (w >= N_ATOMS) return;
    const int lane = threadIdx.x & 31;
    const int deg = w / N_PER_DEG;
    const int rid = w - deg * N_PER_DEG;
    __half* dst = g_Asum + (size_t)w * ASUM_C;
    switch (deg) {
        case 0:  gather_row<1>(atom_repr, bond_repr, a1, b1, rid, w, dst, lane); break;
        case 1:  gather_row<2>(atom_repr, bond_repr, a2, b2, rid, w, dst, lane); break;
        case 2:  gather_row<3>(atom_repr, bond_repr, a3, b3, rid, w, dst, lane); break;
        default: gather_row<4>(atom_repr, bond_repr, a4, b4, rid, w, dst, lane); break;
    }
}

// ---------------- Phase 2: fp16 pipelined GEMM + bias + BN stats ----------------
// 128 threads, 4 warps; warp tile 64(M) x 64(N), grid 2x2. K=320 in 10 chunks of 32
// (2 ksteps of 16), all A from fp16 g_Asum. 3-stage cp.async pipeline.
// Output x stored as fp16 to g_x (stats computed in fp32 pre-rounding).
#define P2_AROW_B   80                               // bytes per A row (32 data halves + pad)
#define P2_A_BYTES  (128 * P2_AROW_B)                // 10240
#define P2_W_BYTES  (2 * 128 * 16 * 2)               // 8192 (2 ksteps)
#define P2_STAGE_B  (P2_A_BYTES + P2_W_BYTES)        // 18432
#define P2_OFF_STATS (3 * P2_STAGE_B)                // 55296
#define P2_SMEM      (P2_OFF_STATS + 1024)           // 56320

__global__ __launch_bounds__(128, 2)
void gemm_kernel(const float* __restrict__ bias) {
    extern __shared__ char smem[];
    float* s_sum = (float*)(smem + P2_OFF_STATS);
    float* s_sq  = s_sum + OUT_C;

    const int tid  = threadIdx.x;
    const int wid  = tid >> 5;
    const int lane = tid & 31;
    const int warp_m = wid & 1;        // 2 M-warps x 64 rows
    const int warp_n = wid >> 1;       // 2 N-warps x 64 cols

    const int d = blockIdx.x & 3;
    const int tile_base = (blockIdx.x >> 2) * TILE_M;
    const int deg_base = d * N_PER_DEG;
    const __half* __restrict__ Wp = g_Wp[d];

    s_sum[tid] = 0.f;                  // blockDim == OUT_C == 128
    s_sq[tid]  = 0.f;

    const uint32_t smem_addr = smem_u32(smem);

    auto issue_stage = [&](int c, int s) {
        const uint32_t aoff = smem_addr + (uint32_t)(s * P2_STAGE_B);
        const uint32_t woff = aoff + (uint32_t)P2_A_BYTES;
#pragma unroll
        for (int i = 0; i < 4; i++) {
            int idx = tid + i * 128;       // 0..511
            int row = idx >> 2;
            int q   = idx & 3;             // 16B segment within the 64B row chunk
            int rg  = tile_base + row;
            if (rg >= N_PER_DEG) rg = N_PER_DEG - 1;
            const __half* asrc = g_Asum + (size_t)(deg_base + rg) * ASUM_C + c * 32 + q * 8;
            CP_ASYNC16(aoff + (uint32_t)(row * P2_AROW_B + q * 16), asrc);
        }
#pragma unroll
        for (int i = 0; i < 4; i++) {
            int idx = tid + i * 128;       // 0..511, 16B each covers the 8192B W block
            CP_ASYNC16(woff + (uint32_t)idx * 16, Wp + (size_t)c * 4096 + idx * 8);
        }
        CP_COMMIT();
    };

    float acc[4][8][4];
#pragma unroll
    for (int mi = 0; mi < 4; mi++)
#pragma unroll
        for (int nb = 0; nb < 8; nb++)
#pragma unroll
            for (int i = 0; i < 4; i++) acc[mi][nb][i] = 0.f;

    issue_stage(0, 0);
    issue_stage(1, 1);

    // ldmatrix per-lane A address (bytes, within stage A block):
    //   lanes 0-7: rows r0-7 col 0 | 8-15: rows 8-15 col 0 | 16-23: rows 0-7 col 16B | 24-31: rows 8-15 col 16B
    const int lm_row = warp_m * 64 + (lane & 7) + ((lane >> 3) & 1) * 8;
    const uint32_t lm_base = (uint32_t)(lm_row * P2_AROW_B + (lane >> 4) * 16);

    // B fragment uint2 offset within a kstep block (512 uint2):
    //   (warp_n*64 + nb*8 + (lane>>2))*4 + (lane&3)
    const int bfrag_off = (warp_n * 64 + (lane >> 2)) * 4 + (lane & 3);

    int s = 0;
#pragma unroll
    for (int c = 0; c < 10; c++) {
        if (c < 9) CP_WAIT1(); else CP_WAIT0();
        __syncthreads();
        if (c + 2 < 10) issue_stage(c + 2, (c + 2) % 3);

        const uint32_t a_stage = smem_addr + (uint32_t)(s * P2_STAGE_B);
        const uint2* Wf = (const uint2*)(smem + (size_t)(s * P2_STAGE_B + P2_A_BYTES));

#pragma unroll
        for (int ks = 0; ks < 2; ks++) {
            uint32_t a[4][4];
#pragma unroll
            for (int mi = 0; mi < 4; mi++)
                ldmatrix_x4(a[mi], a_stage + lm_base + (uint32_t)(mi * 16 * P2_AROW_B + ks * 32));
            const uint2* wst = Wf + ks * 512 + bfrag_off;
#pragma unroll
            for (int nb = 0; nb < 8; nb++) {
                uint2 b = wst[nb * 32];                      // nb*8 n-rows * 4 uint2
#pragma unroll
                for (int mi = 0; mi < 4; mi++)
                    mma_m16n8k16_f16(acc[mi][nb], a[mi], b.x, b.y);
            }
        }
        s = (s == 2) ? 0 : s + 1;
    }

    // ---- epilogue: bias + fp16 streaming store of x + fused BN partial stats (fp32) ----
#pragma unroll
    for (int nb = 0; nb < 8; nb++) {
        const int col0 = warp_n * 64 + nb * 8 + (lane & 3) * 2;
        const float bv0 = __ldg(bias + col0);
        const float bv1 = __ldg(bias + col0 + 1);
        float ps0 = 0.f, ps1 = 0.f, pq0 = 0.f, pq1 = 0.f;
#pragma unroll
        for (int mi = 0; mi < 4; mi++) {
            int gr0 = tile_base + warp_m * 64 + mi * 16 + (lane >> 2);
            float x00 = acc[mi][nb][0] + bv0;
            float x01 = acc[mi][nb][1] + bv1;
            float x10 = acc[mi][nb][2] + bv0;
            float x11 = acc[mi][nb][3] + bv1;
            if (gr0 < N_PER_DEG) {
                __stcs((uint32_t*)(g_x + (size_t)(deg_base + gr0) * OUT_C + col0),
                       pack_f16x2(x00, x01));
                ps0 += x00; ps1 += x01; pq0 += x00 * x00; pq1 += x01 * x01;
            }
            if (gr0 + 8 < N_PER_DEG) {
                __stcs((uint32_t*)(g_x + (size_t)(deg_base + gr0 + 8) * OUT_C + col0),
                       pack_f16x2(x10, x11));
                ps0 += x10; ps1 += x11; pq0 += x10 * x10; pq1 += x11 * x11;
            }
        }
#pragma unroll
        for (int m = 4; m < 32; m <<= 1) {
            ps0 += __shfl_xor_sync(0xffffffffu, ps0, m);
            ps1 += __shfl_xor_sync(0xffffffffu, ps1, m);
            pq0 += __shfl_xor_sync(0xffffffffu, pq0, m);
            pq1 += __shfl_xor_sync(0xffffffffu, pq1, m);
        }
        if ((lane >> 2) == 0) {
            atomicAdd(&s_sum[col0], ps0);
            atomicAdd(&s_sum[col0 + 1], ps1);
            atomicAdd(&s_sq[col0], pq0);
            atomicAdd(&s_sq[col0 + 1], pq1);
        }
    }

    __syncthreads();
    atomicAdd(&g_sum[tid], s_sum[tid]);
    atomicAdd(&g_sumsq[tid], s_sq[tid]);
}

// ---------------- finalize + BN/ReLU ----------------
__global__ void finalize_stats_kernel() {
    int c = threadIdx.x;
    if (c < OUT_C) {
        float mean = g_sum[c] * (1.0f / N_ATOMS);
        float var = g_sumsq[c] * (1.0f / N_ATOMS) - mean * mean;
        g_mean[c] = mean;
        g_istd[c] = rsqrtf(var + BN_EPS);
    }
}

// reads fp16 x (g_x), writes fp32 normalized+ReLU output
__global__ void bn_relu_kernel(float4* __restrict__ out, int n4) {
    int t = blockIdx.x * blockDim.x + threadIdx.x;
    int stride = gridDim.x * blockDim.x;   // multiple of 32
    int c = (t & 31) * 4;
    float m0 = g_mean[c + 0], m1 = g_mean[c + 1], m2 = g_mean[c + 2], m3 = g_mean[c + 3];
    float i0 = g_istd[c + 0], i1 = g_istd[c + 1], i2 = g_istd[c + 2], i3 = g_istd[c + 3];
    const uint2* __restrict__ xh = (const uint2*)g_x;
    for (int i = t; i < n4; i += stride) {
        uint2 p = __ldcs(&xh[i]);
        __half2 h0 = *reinterpret_cast<__half2*>(&p.x);
        __half2 h1 = *reinterpret_cast<__half2*>(&p.y);
        float4 v;
        v.x = fmaxf((__low2float(h0)  - m0) * i0, 0.f);
        v.y = fmaxf((__high2float(h0) - m1) * i1, 0.f);
        v.z = fmaxf((__low2float(h1)  - m2) * i2, 0.f);
        v.w = fmaxf((__high2float(h1) - m3) * i3, 0.f);
        __stcs(&out[i], v);
    }
}

// ---------------- launch ----------------
extern "C" void kernel_launch(void* const* d_in, const int* in_sizes, int n_in,
                              void* d_out, int out_size) {
    (void)n_in; (void)out_size;

    const float* atom_repr = (const float*)d_in[0];
    const float* bond_repr = (const float*)d_in[1];
    const int* aidx[4];
    const int* bidx[4];
    const float* W[4];

    if (in_sizes[4] == OUT_C * (NODE + EDGE)) {
        for (int d = 0; d < 4; d++) {
            aidx[d] = (const int*)d_in[2 + 3 * d];
            bidx[d] = (const int*)d_in[3 + 3 * d];
            W[d]    = (const float*)d_in[4 + 3 * d];
        }
    } else {
        for (int d = 0; d < 4; d++) {
            aidx[d] = (const int*)d_in[2 + d];
            bidx[d] = (const int*)d_in[6 + d];
            W[d]    = (const float*)d_in[10 + d];
        }
    }
    const float* Wself = (const float*)d_in[14];
    const float* bias  = (const float*)d_in[15];
    float* out = (float*)d_out;

    cudaFuncSetAttribute(gemm_kernel, cudaFuncAttributeMaxDynamicSharedMemorySize, P2_SMEM);

    zero_stats_kernel<<<1, 128>>>();
    wconv_kernel<<<(4 * WP_PER_DEG + 255) / 256, 256>>>(W[0], W[1], W[2], W[3], Wself);
    gather_kernel<<<(N_ATOMS * 32) / 256, 256>>>(
        atom_repr, bond_repr,
        aidx[0], aidx[1], aidx[2], aidx[3],
        bidx[0], bidx[1], bidx[2], bidx[3]);
    gemm_kernel<<<4 * N_TILES, 128, P2_SMEM>>>(bias);
    finalize_stats_kernel<<<1, 128>>>();
    const int n4 = (N_ATOMS * OUT_C) / 4;
    bn_relu_kernel<<<2960, 256>>>((float4*)out, n4);
}

// round 16
// speedup vs baseline: 1.0482x; 1.0137x over previous
#include <cuda_runtime.h>
#include <cuda_fp16.h>
#include <cstdint>

// ---------------- problem constants ----------------
#define N_ATOMS   500000
#define N_PER_DEG 125000
#define NODE      128
#define EDGE      64
#define OUT_C     128
#define ASUM_C    320          // halves per row: [0:128) atom sum | [128:192) bond sum | [192:320) self
#define TILE_M    128
#define N_TILES   977          // ceil(125000/128)
#define BN_EPS    1e-5f

__device__ __forceinline__ uint32_t pack_f16x2(float lo, float hi) {
    uint32_t r;
    asm("cvt.rn.f16x2.f32 %0, %1, %2;" : "=r"(r) : "f"(hi), "f"(lo));
    return r;
}

__device__ __forceinline__ void mma_m16n8k16_f16(float d[4], const uint32_t a[4],
                                                 uint32_t b0, uint32_t b1) {
    asm volatile(
        "mma.sync.aligned.m16n8k16.row.col.f32.f16.f16.f32 "
        "{%0,%1,%2,%3}, {%4,%5,%6,%7}, {%8,%9}, {%0,%1,%2,%3};"
        : "+f"(d[0]), "+f"(d[1]), "+f"(d[2]), "+f"(d[3])
        : "r"(a[0]), "r"(a[1]), "r"(a[2]), "r"(a[3]), "r"(b0), "r"(b1));
}

__device__ __forceinline__ void ldmatrix_x4(uint32_t a[4], uint32_t addr) {
    asm volatile(
        "ldmatrix.sync.aligned.m8n8.x4.shared.b16 {%0,%1,%2,%3}, [%4];"
        : "=r"(a[0]), "=r"(a[1]), "=r"(a[2]), "=r"(a[3])
        : "r"(addr));
}

// cp.async helpers
__device__ __forceinline__ uint32_t smem_u32(const void* p) {
    uint32_t a;
    asm("{ .reg .u64 t; cvta.to.shared.u64 t, %1; cvt.u32.u64 %0, t; }" : "=r"(a) : "l"(p));
    return a;
}
#define CP_ASYNC16(dst, src) \
    asm volatile("cp.async.cg.shared.global [%0], [%1], 16;" :: "r"(dst), "l"(src) : "memory")
#define CP_COMMIT() asm volatile("cp.async.commit_group;" ::: "memory")
#define CP_WAIT1()  asm volatile("cp.async.wait_group 1;" ::: "memory")
#define CP_WAIT0()  asm volatile("cp.async.wait_group 0;" ::: "memory")

// ---------------- device scratch (allocation-free) ----------------
__device__ __half g_Asum[(size_t)N_ATOMS * ASUM_C];   // 320 MB, fp16 A (incl. self)
__device__ __half g_x[(size_t)N_ATOMS * OUT_C];       // 128 MB, fp16 pre-BN activations
// W in fp16 B-fragment order. Per degree, per kstep t (0..19, K=16 each), per n (0..127),
// per la3 (0..3): 4 halves = { k=t*16+2*la3, +1, t*16+8+2*la3, +1 } (reg0 pair, reg1 pair).
#define WP_PER_DEG (20 * 128 * 16)                    // 40960 halves
__device__ __half g_Wp[4][WP_PER_DEG];
__device__ float g_sum[OUT_C];
__device__ float g_sumsq[OUT_C];
__device__ float g_mean[OUT_C];
__device__ float g_istd[OUT_C];

// ---------------- K0: zero stats ----------------
__global__ void zero_stats_kernel() {
    if (threadIdx.x < OUT_C) { g_sum[threadIdx.x] = 0.f; g_sumsq[threadIdx.x] = 0.f; }
}

// ---------------- W permute/convert (fp16 fragment order) ----------------
__global__ void wconv_kernel(const float* __restrict__ W1, const float* __restrict__ W2,
                             const float* __restrict__ W3, const float* __restrict__ W4,
                             const float* __restrict__ Wself) {
    int idx = blockIdx.x * blockDim.x + threadIdx.x;
    if (idx >= 4 * WP_PER_DEG) return;
    int d   = idx / WP_PER_DEG;
    int rem = idx - d * WP_PER_DEG;
    int h   = rem & 3;               // which of the 4 halves in the lane's uint2
    int la3 = (rem >> 2) & 3;        // lane&3
    int n   = (rem >> 4) & 127;
    int t   = rem >> 11;             // kstep 0..19
    int k   = t * 16 + ((h < 2) ? (la3 * 2 + h) : (8 + la3 * 2 + (h - 2)));
    const float* Wd = (d == 0) ? W1 : (d == 1) ? W2 : (d == 2) ? W3 : W4;
    float v = (k < 192) ? __ldg(Wd + n * 192 + k) : __ldg(Wself + n * 128 + (k - 192));
    g_Wp[d][rem] = __float2half_rn(v);
}

// ---------------- Phase 1: gather + sum (+self) -> fp16 g_Asum ----------------
template <int DEG>
__device__ __forceinline__
void gather_row(const float* __restrict__ atom_repr, const float* __restrict__ bond_repr,
                const int* __restrict__ ap, const int* __restrict__ bp,
                int rid, int selfrow, __half* __restrict__ dst, int lane) {
    int ai[DEG], bi[DEG];
#pragma unroll
    for (int j = 0; j < DEG; j++) ai[j] = __ldg(ap + rid * DEG + j);
#pragma unroll
    for (int j = 0; j < DEG; j++) bi[j] = __ldg(bp + rid * DEG + j);

    float4 va[DEG];
    float2 vb[DEG];
#pragma unroll
    for (int j = 0; j < DEG; j++)
        va[j] = __ldg((const float4*)(atom_repr + (size_t)ai[j] * NODE) + lane);
#pragma unroll
    for (int j = 0; j < DEG; j++)
        vb[j] = __ldg((const float2*)(bond_repr + (size_t)bi[j] * EDGE) + lane);
    float4 u = __ldg((const float4*)(atom_repr + (size_t)selfrow * NODE) + lane);

    float4 s = va[0];
    float2 t = vb[0];
#pragma unroll
    for (int j = 1; j < DEG; j++) {
        s.x += va[j].x; s.y += va[j].y; s.z += va[j].z; s.w += va[j].w;
        t.x += vb[j].x; t.y += vb[j].y;
    }
    uint2 pa = make_uint2(pack_f16x2(s.x, s.y), pack_f16x2(s.z, s.w));
    uint32_t pb = pack_f16x2(t.x, t.y);
    uint2 pu = make_uint2(pack_f16x2(u.x, u.y), pack_f16x2(u.z, u.w));
    *(uint2*)(dst + lane * 4)           = pa;   // atom sum: halves [0,128)
    *(uint32_t*)(dst + 128 + lane * 2)  = pb;   // bond sum: halves [128,192)
    *(uint2*)(dst + 192 + lane * 4)     = pu;   // self:     halves [192,320)
}

__global__ __launch_bounds__(256)
void gather_kernel(const float* __restrict__ atom_repr, const float* __restrict__ bond_repr,
                   const int* __restrict__ a1, const int* __restrict__ a2,
                   const int* __restrict__ a3, const int* __restrict__ a4,
                   const int* __restrict__ b1, const int* __restrict__ b2,
                   const int* __restrict__ b3, const int* __restrict__ b4) {
    const int w = (blockIdx.x * 256 + threadIdx.x) >> 5;   // one warp per row
    if (w >= N_ATOMS) return;
    const int lane = threadIdx.x & 31;
    const int deg = w / N_PER_DEG;
    const int rid = w - deg * N_PER_DEG;
    __half* dst = g_Asum + (size_t)w * ASUM_C;
    switch (deg) {
        case 0:  gather_row<1>(atom_repr, bond_repr, a1, b1, rid, w, dst, lane); break;
        case 1:  gather_row<2>(atom_repr, bond_repr, a2, b2, rid, w, dst, lane); break;
        case 2:  gather_row<3>(atom_repr, bond_repr, a3, b3, rid, w, dst, lane); break;
        default: gather_row<4>(atom_repr, bond_repr, a4, b4, rid, w, dst, lane); break;
    }
}

// ---------------- Phase 2: fp16 pipelined GEMM + bias + BN stats ----------------
// 256 threads, 8 warps; warp tile 64(M) x 32(N), warp grid 2(M) x 4(N); CTA tile 128x128.
// 16 warps/SM (2 CTAs) for latency hiding. K=320 in 10 chunks of 32 (2 ksteps of 16).
// 3-stage cp.async pipeline; A via ldmatrix.x4, W via conflict-free LDS.64 fragment order.
// Output x stored as fp16 to g_x (stats computed in fp32 pre-rounding).
#define P2_AROW_B   80                               // bytes per A row (32 data halves + pad)
#define P2_A_BYTES  (128 * P2_AROW_B)                // 10240
#define P2_W_BYTES  (2 * 128 * 16 * 2)               // 8192 (2 ksteps)
#define P2_STAGE_B  (P2_A_BYTES + P2_W_BYTES)        // 18432
#define P2_OFF_STATS (3 * P2_STAGE_B)                // 55296
#define P2_SMEM      (P2_OFF_STATS + 1024)           // 56320

__global__ __launch_bounds__(256, 2)
void gemm_kernel(const float* __restrict__ bias) {
    extern __shared__ char smem[];
    float* s_sum = (float*)(smem + P2_OFF_STATS);
    float* s_sq  = s_sum + OUT_C;

    const int tid  = threadIdx.x;
    const int wid  = tid >> 5;
    const int lane = tid & 31;
    const int warp_m = wid & 1;        // 2 M-warps x 64 rows
    const int warp_n = wid >> 1;       // 4 N-warps x 32 cols

    const int d = blockIdx.x & 3;
    const int tile_base = (blockIdx.x >> 2) * TILE_M;
    const int deg_base = d * N_PER_DEG;
    const __half* __restrict__ Wp = g_Wp[d];

    if (tid < OUT_C) { s_sum[tid] = 0.f; s_sq[tid] = 0.f; }

    const uint32_t smem_addr = smem_u32(smem);

    auto issue_stage = [&](int c, int s) {
        const uint32_t aoff = smem_addr + (uint32_t)(s * P2_STAGE_B);
        const uint32_t woff = aoff + (uint32_t)P2_A_BYTES;
#pragma unroll
        for (int i = 0; i < 2; i++) {
            int idx = tid + i * 256;       // 0..511
            int row = idx >> 2;
            int q   = idx & 3;             // 16B segment within the 64B row chunk
            int rg  = tile_base + row;
            if (rg >= N_PER_DEG) rg = N_PER_DEG - 1;
            const __half* asrc = g_Asum + (size_t)(deg_base + rg) * ASUM_C + c * 32 + q * 8;
            CP_ASYNC16(aoff + (uint32_t)(row * P2_AROW_B + q * 16), asrc);
        }
#pragma unroll
        for (int i = 0; i < 2; i++) {
            int idx = tid + i * 256;       // 0..511, 16B each covers the 8192B W block
            CP_ASYNC16(woff + (uint32_t)idx * 16, Wp + (size_t)c * 4096 + idx * 8);
        }
        CP_COMMIT();
    };

    float acc[4][4][4];
#pragma unroll
    for (int mi = 0; mi < 4; mi++)
#pragma unroll
        for (int nb = 0; nb < 4; nb++)
#pragma unroll
            for (int i = 0; i < 4; i++) acc[mi][nb][i] = 0.f;

    issue_stage(0, 0);
    issue_stage(1, 1);

    // ldmatrix per-lane A address (bytes, within stage A block):
    //   lanes 0-7: rows r0-7 col 0 | 8-15: rows 8-15 col 0 | 16-23: rows 0-7 col 16B | 24-31: rows 8-15 col 16B
    const int lm_row = warp_m * 64 + (lane & 7) + ((lane >> 3) & 1) * 8;
    const uint32_t lm_base = (uint32_t)(lm_row * P2_AROW_B + (lane >> 4) * 16);

    // B fragment uint2 offset within a kstep block (512 uint2):
    //   (warp_n*32 + nb*8 + (lane>>2))*4 + (lane&3)
    const int bfrag_off = (warp_n * 32 + (lane >> 2)) * 4 + (lane & 3);

    int s = 0;
#pragma unroll
    for (int c = 0; c < 10; c++) {
        if (c < 9) CP_WAIT1(); else CP_WAIT0();
        __syncthreads();
        if (c + 2 < 10) issue_stage(c + 2, (c + 2) % 3);

        const uint32_t a_stage = smem_addr + (uint32_t)(s * P2_STAGE_B);
        const uint2* Wf = (const uint2*)(smem + (size_t)(s * P2_STAGE_B + P2_A_BYTES));

#pragma unroll
        for (int ks = 0; ks < 2; ks++) {
            uint32_t a[4][4];
#pragma unroll
            for (int mi = 0; mi < 4; mi++)
                ldmatrix_x4(a[mi], a_stage + lm_base + (uint32_t)(mi * 16 * P2_AROW_B + ks * 32));
            const uint2* wst = Wf + ks * 512 + bfrag_off;
#pragma unroll
            for (int nb = 0; nb < 4; nb++) {
                uint2 b = wst[nb * 32];                      // nb*8 n-rows * 4 uint2
#pragma unroll
                for (int mi = 0; mi < 4; mi++)
                    mma_m16n8k16_f16(acc[mi][nb], a[mi], b.x, b.y);
            }
        }
        s = (s == 2) ? 0 : s + 1;
    }

    // ---- epilogue: bias + fp16 streaming store of x + fused BN partial stats (fp32) ----
#pragma unroll
    for (int nb = 0; nb < 4; nb++) {
        const int col0 = warp_n * 32 + nb * 8 + (lane & 3) * 2;
        const float bv0 = __ldg(bias + col0);
        const float bv1 = __ldg(bias + col0 + 1);
        float ps0 = 0.f, ps1 = 0.f, pq0 = 0.f, pq1 = 0.f;
#pragma unroll
        for (int mi = 0; mi < 4; mi++) {
            int gr0 = tile_base + warp_m * 64 + mi * 16 + (lane >> 2);
            float x00 = acc[mi][nb][0] + bv0;
            float x01 = acc[mi][nb][1] + bv1;
            float x10 = acc[mi][nb][2] + bv0;
            float x11 = acc[mi][nb][3] + bv1;
            if (gr0 < N_PER_DEG) {
                __stcs((uint32_t*)(g_x + (size_t)(deg_base + gr0) * OUT_C + col0),
                       pack_f16x2(x00, x01));
                ps0 += x00; ps1 += x01; pq0 += x00 * x00; pq1 += x01 * x01;
            }
            if (gr0 + 8 < N_PER_DEG) {
                __stcs((uint32_t*)(g_x + (size_t)(deg_base + gr0 + 8) * OUT_C + col0),
                       pack_f16x2(x10, x11));
                ps0 += x10; ps1 += x11; pq0 += x10 * x10; pq1 += x11 * x11;
            }
        }
#pragma unroll
        for (int m = 4; m < 32; m <<= 1) {
            ps0 += __shfl_xor_sync(0xffffffffu, ps0, m);
            ps1 += __shfl_xor_sync(0xffffffffu, ps1, m);
            pq0 += __shfl_xor_sync(0xffffffffu, pq0, m);
            pq1 += __shfl_xor_sync(0xffffffffu, pq1, m);
        }
        if ((lane >> 2) == 0) {
            atomicAdd(&s_sum[col0], ps0);
            atomicAdd(&s_sum[col0 + 1], ps1);
            atomicAdd(&s_sq[col0], pq0);
            atomicAdd(&s_sq[col0 + 1], pq1);
        }
    }

    __syncthreads();
    if (tid < OUT_C) {
        atomicAdd(&g_sum[tid], s_sum[tid]);
        atomicAdd(&g_sumsq[tid], s_sq[tid]);
    }
}

// ---------------- finalize + BN/ReLU ----------------
__global__ void finalize_stats_kernel() {
    int c = threadIdx.x;
    if (c < OUT_C) {
        float mean = g_sum[c] * (1.0f / N_ATOMS);
        float var = g_sumsq[c] * (1.0f / N_ATOMS) - mean * mean;
        g_mean[c] = mean;
        g_istd[c] = rsqrtf(var + BN_EPS);
    }
}

// reads fp16 x (g_x), writes fp32 normalized+ReLU output
__global__ void bn_relu_kernel(float4* __restrict__ out, int n4) {
    int t = blockIdx.x * blockDim.x + threadIdx.x;
    int stride = gridDim.x * blockDim.x;   // multiple of 32
    int c = (t & 31) * 4;
    float m0 = g_mean[c + 0], m1 = g_mean[c + 1], m2 = g_mean[c + 2], m3 = g_mean[c + 3];
    float i0 = g_istd[c + 0], i1 = g_istd[c + 1], i2 = g_istd[c + 2], i3 = g_istd[c + 3];
    const uint2* __restrict__ xh = (const uint2*)g_x;
    for (int i = t; i < n4; i += stride) {
        uint2 p = __ldcs(&xh[i]);
        __half2 h0 = *reinterpret_cast<__half2*>(&p.x);
        __half2 h1 = *reinterpret_cast<__half2*>(&p.y);
        float4 v;
        v.x = fmaxf((__low2float(h0)  - m0) * i0, 0.f);
        v.y = fmaxf((__high2float(h0) - m1) * i1, 0.f);
        v.z = fmaxf((__low2float(h1)  - m2) * i2, 0.f);
        v.w = fmaxf((__high2float(h1) - m3) * i3, 0.f);
        __stcs(&out[i], v);
    }
}

// ---------------- launch ----------------
extern "C" void kernel_launch(void* const* d_in, const int* in_sizes, int n_in,
                              void* d_out, int out_size) {
    (void)n_in; (void)out_size;

    const float* atom_repr = (const float*)d_in[0];
    const float* bond_repr = (const float*)d_in[1];
    const int* aidx[4];
    const int* bidx[4];
    const float* W[4];

    if (in_sizes[4] == OUT_C * (NODE + EDGE)) {
        for (int d = 0; d < 4; d++) {
            aidx[d] = (const int*)d_in[2 + 3 * d];
            bidx[d] = (const int*)d_in[3 + 3 * d];
            W[d]    = (const float*)d_in[4 + 3 * d];
        }
    } else {
        for (int d = 0; d < 4; d++) {
            aidx[d] = (const int*)d_in[2 + d];
            bidx[d] = (const int*)d_in[6 + d];
            W[d]    = (const float*)d_in[10 + d];
        }
    }
    const float* Wself = (const float*)d_in[14];
    const float* bias  = (const float*)d_in[15];
    float* out = (float*)d_out;

    cudaFuncSetAttribute(gemm_kernel, cudaFuncAttributeMaxDynamicSharedMemorySize, P2_SMEM);

    zero_stats_kernel<<<1, 128>>>();
    wconv_kernel<<<(4 * WP_PER_DEG + 255) / 256, 256>>>(W[0], W[1], W[2], W[3], Wself);
    gather_kernel<<<(N_ATOMS * 32) / 256, 256>>>(
        atom_repr, bond_repr,
        aidx[0], aidx[1], aidx[2], aidx[3],
        bidx[0], bidx[1], bidx[2], bidx[3]);
    gemm_kernel<<<4 * N_TILES, 256, P2_SMEM>>>(bias);
    finalize_stats_kernel<<<1, 128>>>();
    const int n4 = (N_ATOMS * OUT_C) / 4;
    bn_relu_kernel<<<2960, 256>>>((float4*)out, n4);
}

// round 17
// speedup vs baseline: 1.0533x; 1.0049x over previous
#include <cuda_runtime.h>
#include <cuda_fp16.h>
#include <cstdint>

// ---------------- problem constants ----------------
#define N_ATOMS   500000
#define N_PER_DEG 125000
#define NODE      128
#define EDGE      64
#define OUT_C     128
#define ASUM_C    320          // halves per row: [0:128) atom sum | [128:192) bond sum | [192:320) self
#define TILE_M    128
#define N_TILES   977          // ceil(125000/128)
#define BN_EPS    1e-5f

__device__ __forceinline__ uint32_t pack_f16x2(float lo, float hi) {
    uint32_t r;
    asm("cvt.rn.f16x2.f32 %0, %1, %2;" : "=r"(r) : "f"(hi), "f"(lo));
    return r;
}

__device__ __forceinline__ void mma_m16n8k16_f16(float d[4], const uint32_t a[4],
                                                 uint32_t b0, uint32_t b1) {
    asm volatile(
        "mma.sync.aligned.m16n8k16.row.col.f32.f16.f16.f32 "
        "{%0,%1,%2,%3}, {%4,%5,%6,%7}, {%8,%9}, {%0,%1,%2,%3};"
        : "+f"(d[0]), "+f"(d[1]), "+f"(d[2]), "+f"(d[3])
        : "r"(a[0]), "r"(a[1]), "r"(a[2]), "r"(a[3]), "r"(b0), "r"(b1));
}

__device__ __forceinline__ void ldmatrix_x4(uint32_t a[4], uint32_t addr) {
    asm volatile(
        "ldmatrix.sync.aligned.m8n8.x4.shared.b16 {%0,%1,%2,%3}, [%4];"
        : "=r"(a[0]), "=r"(a[1]), "=r"(a[2]), "=r"(a[3])
        : "r"(addr));
}

// cp.async helpers
__device__ __forceinline__ uint32_t smem_u32(const void* p) {
    uint32_t a;
    asm("{ .reg .u64 t; cvta.to.shared.u64 t, %1; cvt.u32.u64 %0, t; }" : "=r"(a) : "l"(p));
    return a;
}
#define CP_ASYNC16(dst, src) \
    asm volatile("cp.async.cg.shared.global [%0], [%1], 16;" :: "r"(dst), "l"(src) : "memory")
#define CP_COMMIT() asm volatile("cp.async.commit_group;" ::: "memory")
#define CP_WAIT2()  asm volatile("cp.async.wait_group 2;" ::: "memory")
#define CP_WAIT1()  asm volatile("cp.async.wait_group 1;" ::: "memory")
#define CP_WAIT0()  asm volatile("cp.async.wait_group 0;" ::: "memory")

// ---------------- device scratch (allocation-free) ----------------
__device__ __half g_Asum[(size_t)N_ATOMS * ASUM_C];   // 320 MB, fp16 A (incl. self)
__device__ __half g_x[(size_t)N_ATOMS * OUT_C];       // 128 MB, fp16 pre-BN activations
// W in fp16 B-fragment order. Per degree, per kstep t (0..19, K=16 each), per n (0..127),
// per la3 (0..3): 4 halves = { k=t*16+2*la3, +1, t*16+8+2*la3, +1 } (reg0 pair, reg1 pair).
#define WP_PER_DEG (20 * 128 * 16)                    // 40960 halves
__device__ __half g_Wp[4][WP_PER_DEG];
__device__ float g_sum[OUT_C];
__device__ float g_sumsq[OUT_C];
__device__ float g_mean[OUT_C];
__device__ float g_istd[OUT_C];

// ---------------- K0: zero stats ----------------
__global__ void zero_stats_kernel() {
    if (threadIdx.x < OUT_C) { g_sum[threadIdx.x] = 0.f; g_sumsq[threadIdx.x] = 0.f; }
}

// ---------------- W permute/convert (fp16 fragment order) ----------------
__global__ void wconv_kernel(const float* __restrict__ W1, const float* __restrict__ W2,
                             const float* __restrict__ W3, const float* __restrict__ W4,
                             const float* __restrict__ Wself) {
    int idx = blockIdx.x * blockDim.x + threadIdx.x;
    if (idx >= 4 * WP_PER_DEG) return;
    int d   = idx / WP_PER_DEG;
    int rem = idx - d * WP_PER_DEG;
    int h   = rem & 3;               // which of the 4 halves in the lane's uint2
    int la3 = (rem >> 2) & 3;        // lane&3
    int n   = (rem >> 4) & 127;
    int t   = rem >> 11;             // kstep 0..19
    int k   = t * 16 + ((h < 2) ? (la3 * 2 + h) : (8 + la3 * 2 + (h - 2)));
    const float* Wd = (d == 0) ? W1 : (d == 1) ? W2 : (d == 2) ? W3 : W4;
    float v = (k < 192) ? __ldg(Wd + n * 192 + k) : __ldg(Wself + n * 128 + (k - 192));
    g_Wp[d][rem] = __float2half_rn(v);
}

// ---------------- Phase 1: gather + sum (+self) -> fp16 g_Asum ----------------
template <int DEG>
__device__ __forceinline__
void gather_row(const float* __restrict__ atom_repr, const float* __restrict__ bond_repr,
                const int* __restrict__ ap, const int* __restrict__ bp,
                int rid, int selfrow, __half* __restrict__ dst, int lane) {
    int ai[DEG], bi[DEG];
#pragma unroll
    for (int j = 0; j < DEG; j++) ai[j] = __ldg(ap + rid * DEG + j);
#pragma unroll
    for (int j = 0; j < DEG; j++) bi[j] = __ldg(bp + rid * DEG + j);

    float4 va[DEG];
    float2 vb[DEG];
#pragma unroll
    for (int j = 0; j < DEG; j++)
        va[j] = __ldg((const float4*)(atom_repr + (size_t)ai[j] * NODE) + lane);
#pragma unroll
    for (int j = 0; j < DEG; j++)
        vb[j] = __ldg((const float2*)(bond_repr + (size_t)bi[j] * EDGE) + lane);
    float4 u = __ldg((const float4*)(atom_repr + (size_t)selfrow * NODE) + lane);

    float4 s = va[0];
    float2 t = vb[0];
#pragma unroll
    for (int j = 1; j < DEG; j++) {
        s.x += va[j].x; s.y += va[j].y; s.z += va[j].z; s.w += va[j].w;
        t.x += vb[j].x; t.y += vb[j].y;
    }
    uint2 pa = make_uint2(pack_f16x2(s.x, s.y), pack_f16x2(s.z, s.w));
    uint32_t pb = pack_f16x2(t.x, t.y);
    uint2 pu = make_uint2(pack_f16x2(u.x, u.y), pack_f16x2(u.z, u.w));
    *(uint2*)(dst + lane * 4)           = pa;   // atom sum: halves [0,128)
    *(uint32_t*)(dst + 128 + lane * 2)  = pb;   // bond sum: halves [128,192)
    *(uint2*)(dst + 192 + lane * 4)     = pu;   // self:     halves [192,320)
}

__global__ __launch_bounds__(256)
void gather_kernel(const float* __restrict__ atom_repr, const float* __restrict__ bond_repr,
                   const int* __restrict__ a1, const int* __restrict__ a2,
                   const int* __restrict__ a3, const int* __restrict__ a4,
                   const int* __restrict__ b1, const int* __restrict__ b2,
                   const int* __restrict__ b3, const int* __restrict__ b4) {
    const int w = (blockIdx.x * 256 + threadIdx.x) >> 5;   // one warp per row
    if (w >= N_ATOMS) return;
    const int lane = threadIdx.x & 31;
    const int deg = w / N_PER_DEG;
    const int rid = w - deg * N_PER_DEG;
    __half* dst = g_Asum + (size_t)w * ASUM_C;
    switch (deg) {
        case 0:  gather_row<1>(atom_repr, bond_repr, a1, b1, rid, w, dst, lane); break;
        case 1:  gather_row<2>(atom_repr, bond_repr, a2, b2, rid, w, dst, lane); break;
        case 2:  gather_row<3>(atom_repr, bond_repr, a3, b3, rid, w, dst, lane); break;
        default: gather_row<4>(atom_repr, bond_repr, a4, b4, rid, w, dst, lane); break;
    }
}

// ---------------- Phase 2: fp16 pipelined GEMM + bias + BN stats ----------------
// 256 threads, 8 warps; warp tile 64(M) x 32(N), warp grid 2(M) x 4(N); CTA tile 128x128.
// 16 warps/SM (2 CTAs). K=320 in 10 chunks of 32 (2 ksteps of 16).
// 4-stage cp.async pipeline with wait_group 2 (two chunks of latency slack).
// A via ldmatrix.x4, W via conflict-free LDS.64 fragment order.
// Output x stored as fp16 to g_x (stats computed in fp32 pre-rounding).
#define P2_AROW_B   80                               // bytes per A row (32 data halves + pad)
#define P2_A_BYTES  (128 * P2_AROW_B)                // 10240
#define P2_W_BYTES  (2 * 128 * 16 * 2)               // 8192 (2 ksteps)
#define P2_STAGE_B  (P2_A_BYTES + P2_W_BYTES)        // 18432
#define P2_N_STAGES 4
#define P2_OFF_STATS (P2_N_STAGES * P2_STAGE_B)      // 73728
#define P2_SMEM      (P2_OFF_STATS + 1024)           // 74752

__global__ __launch_bounds__(256, 2)
void gemm_kernel(const float* __restrict__ bias) {
    extern __shared__ char smem[];
    float* s_sum = (float*)(smem + P2_OFF_STATS);
    float* s_sq  = s_sum + OUT_C;

    const int tid  = threadIdx.x;
    const int wid  = tid >> 5;
    const int lane = tid & 31;
    const int warp_m = wid & 1;        // 2 M-warps x 64 rows
    const int warp_n = wid >> 1;       // 4 N-warps x 32 cols

    const int d = blockIdx.x & 3;
    const int tile_base = (blockIdx.x >> 2) * TILE_M;
    const int deg_base = d * N_PER_DEG;
    const __half* __restrict__ Wp = g_Wp[d];

    if (tid < OUT_C) { s_sum[tid] = 0.f; s_sq[tid] = 0.f; }

    const uint32_t smem_addr = smem_u32(smem);

    auto issue_stage = [&](int c) {
        const int s = c & 3;
        const uint32_t aoff = smem_addr + (uint32_t)(s * P2_STAGE_B);
        const uint32_t woff = aoff + (uint32_t)P2_A_BYTES;
#pragma unroll
        for (int i = 0; i < 2; i++) {
            int idx = tid + i * 256;       // 0..511
            int row = idx >> 2;
            int q   = idx & 3;             // 16B segment within the 64B row chunk
            int rg  = tile_base + row;
            if (rg >= N_PER_DEG) rg = N_PER_DEG - 1;
            const __half* asrc = g_Asum + (size_t)(deg_base + rg) * ASUM_C + c * 32 + q * 8;
            CP_ASYNC16(aoff + (uint32_t)(row * P2_AROW_B + q * 16), asrc);
        }
#pragma unroll
        for (int i = 0; i < 2; i++) {
            int idx = tid + i * 256;       // 0..511, 16B each covers the 8192B W block
            CP_ASYNC16(woff + (uint32_t)idx * 16, Wp + (size_t)c * 4096 + idx * 8);
        }
        CP_COMMIT();
    };

    float acc[4][4][4];
#pragma unroll
    for (int mi = 0; mi < 4; mi++)
#pragma unroll
        for (int nb = 0; nb < 4; nb++)
#pragma unroll
            for (int i = 0; i < 4; i++) acc[mi][nb][i] = 0.f;

    issue_stage(0);
    issue_stage(1);
    issue_stage(2);

    // ldmatrix per-lane A address (bytes, within stage A block):
    //   lanes 0-7: rows r0-7 col 0 | 8-15: rows 8-15 col 0 | 16-23: rows 0-7 col 16B | 24-31: rows 8-15 col 16B
    const int lm_row = warp_m * 64 + (lane & 7) + ((lane >> 3) & 1) * 8;
    const uint32_t lm_base = (uint32_t)(lm_row * P2_AROW_B + (lane >> 4) * 16);

    // B fragment uint2 offset within a kstep block (512 uint2):
    //   (warp_n*32 + nb*8 + (lane>>2))*4 + (lane&3)
    const int bfrag_off = (warp_n * 32 + (lane >> 2)) * 4 + (lane & 3);

#pragma unroll
    for (int c = 0; c < 10; c++) {
        if (c < 8) CP_WAIT2();
        else if (c == 8) CP_WAIT1();
        else CP_WAIT0();
        __syncthreads();
        if (c + 3 < 10) issue_stage(c + 3);

        const int s = c & 3;
        const uint32_t a_stage = smem_addr + (uint32_t)(s * P2_STAGE_B);
        const uint2* Wf = (const uint2*)(smem + (size_t)(s * P2_STAGE_B + P2_A_BYTES));

#pragma unroll
        for (int ks = 0; ks < 2; ks++) {
            uint32_t a[4][4];
#pragma unroll
            for (int mi = 0; mi < 4; mi++)
                ldmatrix_x4(a[mi], a_stage + lm_base + (uint32_t)(mi * 16 * P2_AROW_B + ks * 32));
            const uint2* wst = Wf + ks * 512 + bfrag_off;
#pragma unroll
            for (int nb = 0; nb < 4; nb++) {
                uint2 b = wst[nb * 32];                      // nb*8 n-rows * 4 uint2
#pragma unroll
                for (int mi = 0; mi < 4; mi++)
                    mma_m16n8k16_f16(acc[mi][nb], a[mi], b.x, b.y);
            }
        }
    }

    // ---- epilogue: bias + fp16 streaming store of x + fused BN partial stats (fp32) ----
#pragma unroll
    for (int nb = 0; nb < 4; nb++) {
        const int col0 = warp_n * 32 + nb * 8 + (lane & 3) * 2;
        const float bv0 = __ldg(bias + col0);
        const float bv1 = __ldg(bias + col0 + 1);
        float ps0 = 0.f, ps1 = 0.f, pq0 = 0.f, pq1 = 0.f;
#pragma unroll
        for (int mi = 0; mi < 4; mi++) {
            int gr0 = tile_base + warp_m * 64 + mi * 16 + (lane >> 2);
            float x00 = acc[mi][nb][0] + bv0;
            float x01 = acc[mi][nb][1] + bv1;
            float x10 = acc[mi][nb][2] + bv0;
            float x11 = acc[mi][nb][3] + bv1;
            if (gr0 < N_PER_DEG) {
                __stcs((uint32_t*)(g_x + (size_t)(deg_base + gr0) * OUT_C + col0),
                       pack_f16x2(x00, x01));
                ps0 += x00; ps1 += x01; pq0 += x00 * x00; pq1 += x01 * x01;
            }
            if (gr0 + 8 < N_PER_DEG) {
                __stcs((uint32_t*)(g_x + (size_t)(deg_base + gr0 + 8) * OUT_C + col0),
                       pack_f16x2(x10, x11));
                ps0 += x10; ps1 += x11; pq0 += x10 * x10; pq1 += x11 * x11;
            }
        }
#pragma unroll
        for (int m = 4; m < 32; m <<= 1) {
            ps0 += __shfl_xor_sync(0xffffffffu, ps0, m);
            ps1 += __shfl_xor_sync(0xffffffffu, ps1, m);
            pq0 += __shfl_xor_sync(0xffffffffu, pq0, m);
            pq1 += __shfl_xor_sync(0xffffffffu, pq1, m);
        }
        if ((lane >> 2) == 0) {
            atomicAdd(&s_sum[col0], ps0);
            atomicAdd(&s_sum[col0 + 1], ps1);
            atomicAdd(&s_sq[col0], pq0);
            atomicAdd(&s_sq[col0 + 1], pq1);
        }
    }

    __syncthreads();
    if (tid < OUT_C) {
        atomicAdd(&g_sum[tid], s_sum[tid]);
        atomicAdd(&g_sumsq[tid], s_sq[tid]);
    }
}

// ---------------- finalize + BN/ReLU ----------------
__global__ void finalize_stats_kernel() {
    int c = threadIdx.x;
    if (c < OUT_C) {
        float mean = g_sum[c] * (1.0f / N_ATOMS);
        float var = g_sumsq[c] * (1.0f / N_ATOMS) - mean * mean;
        g_mean[c] = mean;
        g_istd[c] = rsqrtf(var + BN_EPS);
    }
}

// reads fp16 x (g_x), writes fp32 normalized+ReLU output
__global__ void bn_relu_kernel(float4* __restrict__ out, int n4) {
    int t = blockIdx.x * blockDim.x + threadIdx.x;
    int stride = gridDim.x * blockDim.x;   // multiple of 32
    int c = (t & 31) * 4;
    float m0 = g_mean[c + 0], m1 = g_mean[c + 1], m2 = g_mean[c + 2], m3 = g_mean[c + 3];
    float i0 = g_istd[c + 0], i1 = g_istd[c + 1], i2 = g_istd[c + 2], i3 = g_istd[c + 3];
    const uint2* __restrict__ xh = (const uint2*)g_x;
    for (int i = t; i < n4; i += stride) {
        uint2 p = __ldcs(&xh[i]);
        __half2 h0 = *reinterpret_cast<__half2*>(&p.x);
        __half2 h1 = *reinterpret_cast<__half2*>(&p.y);
        float4 v;
        v.x = fmaxf((__low2float(h0)  - m0) * i0, 0.f);
        v.y = fmaxf((__high2float(h0) - m1) * i1, 0.f);
        v.z = fmaxf((__low2float(h1)  - m2) * i2, 0.f);
        v.w = fmaxf((__high2float(h1) - m3) * i3, 0.f);
        __stcs(&out[i], v);
    }
}

// ---------------- launch ----------------
extern "C" void kernel_launch(void* const* d_in, const int* in_sizes, int n_in,
                              void* d_out, int out_size) {
    (void)n_in; (void)out_size;

    const float* atom_repr = (const float*)d_in[0];
    const float* bond_repr = (const float*)d_in[1];
    const int* aidx[4];
    const int* bidx[4];
    const float* W[4];

    if (in_sizes[4] == OUT_C * (NODE + EDGE)) {
        for (int d = 0; d < 4; d++) {
            aidx[d] = (const int*)d_in[2 + 3 * d];
            bidx[d] = (const int*)d_in[3 + 3 * d];
            W[d]    = (const float*)d_in[4 + 3 * d];
        }
    } else {
        for (int d = 0; d < 4; d++) {
            aidx[d] = (const int*)d_in[2 + d];
            bidx[d] = (const int*)d_in[6 + d];
            W[d]    = (const float*)d_in[10 + d];
        }
    }
    const float* Wself = (const float*)d_in[14];
    const float* bias  = (const float*)d_in[15];
    float* out = (float*)d_out;

    cudaFuncSetAttribute(gemm_kernel, cudaFuncAttributeMaxDynamicSharedMemorySize, P2_SMEM);

    zero_stats_kernel<<<1, 128>>>();
    wconv_kernel<<<(4 * WP_PER_DEG + 255) / 256, 256>>>(W[0], W[1], W[2], W[3], Wself);
    gather_kernel<<<(N_ATOMS * 32) / 256, 256>>>(
        atom_repr, bond_repr,
        aidx[0], aidx[1], aidx[2], aidx[3],
        bidx[0], bidx[1], bidx[2], bidx[3]);
    gemm_kernel<<<4 * N_TILES, 256, P2_SMEM>>>(bias);
    finalize_stats_kernel<<<1, 128>>>();
    const int n4 = (N_ATOMS * OUT_C) / 4;
    bn_relu_kernel<<<2960, 256>>>((float4*)out, n4);
}